// round 12
// baseline (speedup 1.0000x reference)
#include <cuda_runtime.h>
#include <cuda_fp16.h>
#include <cstdint>
#include <cstddef>

// ---------------- problem shape ----------------
#define B_  256
#define F_  784
#define T_  128
#define U_  2048
#define KP  832            // K padded to 13*64 (zeros beyond 784 contribute 0)
#define KC  64             // k per chunk
#define NCH 13             // KP/KC
#define NT  128            // u-tile per CTA

#define ALPHA_  0.9f
#define BETA_   0.85f
#define THRESH_ 1.0f
#define SPLIT_SCALE 2048.0f
#define INV_SCALE (1.0f / 2048.0f)

// smem stage: 4 arrays (A0,A1,B0,B1) of [128 rows][72 halfs] (64 data + 8 pad)
#define ROWH    72
#define ARR_B   (128 * ROWH * 2)      // 18432
#define STAGE_B (4 * ARR_B)           // 73728
#define SMEM_TOTAL (2 * STAGE_B)      // 147456 (epilogue Cs 128*132*4=67584 aliases)

// ---------------- scratch (device globals; allocation-free rule) ----------
__device__ __half X0d[B_][T_][KP];    // 54.5 MB  main split of x, K-major
__device__ __half X1d[B_][T_][KP];    // 54.5 MB  residual*2048
__device__ __half W0d[U_][KP];        // 3.4 MB
__device__ __half W1d[U_][KP];        // 3.4 MB

// ---------------- PTX helpers (all baseline sm_80 ISA -> compute_103 OK) ---
__device__ __forceinline__ void cp_async16(uint32_t saddr, const void* g) {
    asm volatile("cp.async.cg.shared.global [%0], [%1], 16;"
                 :: "r"(saddr), "l"(g) : "memory");
}
__device__ __forceinline__ void cp_commit() {
    asm volatile("cp.async.commit_group;" ::: "memory");
}
__device__ __forceinline__ void cp_wait1() {
    asm volatile("cp.async.wait_group 1;" ::: "memory");
}
__device__ __forceinline__ void cp_wait0() {
    asm volatile("cp.async.wait_group 0;" ::: "memory");
}
// plain (non-trans) ldmatrix x4: lane l gets M[l/4][2*(l%4)..+1] per 8x8 mat.
__device__ __forceinline__ void ldsm4(uint32_t* r, uint32_t addr) {
    asm volatile("ldmatrix.sync.aligned.m8n8.x4.shared.b16 {%0,%1,%2,%3}, [%4];"
                 : "=r"(r[0]), "=r"(r[1]), "=r"(r[2]), "=r"(r[3]) : "r"(addr));
}
__device__ __forceinline__ void mma16816(float* c, const uint32_t* a, const uint32_t* b) {
    asm volatile(
        "mma.sync.aligned.m16n8k16.row.col.f32.f16.f16.f32 "
        "{%0,%1,%2,%3}, {%4,%5,%6,%7}, {%8,%9}, {%0,%1,%2,%3};"
        : "+f"(c[0]), "+f"(c[1]), "+f"(c[2]), "+f"(c[3])
        : "r"(a[0]), "r"(a[1]), "r"(a[2]), "r"(a[3]), "r"(b[0]), "r"(b[1]));
}
// packed fp16x2 multiply (exact for power-of-two scales; results stay normal)
__device__ __forceinline__ uint32_t hmul2(uint32_t a, uint32_t s) {
    uint32_t d;
    asm("mul.f16x2 %0, %1, %2;" : "=r"(d) : "r"(a), "r"(s));
    return d;
}
#define SCALE_A_2M5 0x28002800u   // half2(2^-5, 2^-5)
#define SCALE_B_2M6 0x24002400u   // half2(2^-6, 2^-6)
__device__ __forceinline__ uint32_t s2u(const void* p) {
    return (uint32_t)__cvta_generic_to_shared(p);
}

// ---------------- split precompute (unchanged from R11, bit-exact) --------
__global__ void split_x_kernel(const float* __restrict__ x) {
    __shared__ float tile[32][33];
    const int b  = blockIdx.z;
    const int f0 = blockIdx.x * 32;
    const int t0 = blockIdx.y * 32;
    const int tx = threadIdx.x, ty = threadIdx.y;
    const int tid = ty * 32 + tx;
    for (int i = ty; i < 32; i += 8) {
        const int f = f0 + i;
        float v = 0.f;
        if (f < F_) v = x[((size_t)b * F_ + f) * T_ + t0 + tx];
        tile[i][tx] = v;
    }
    __syncthreads();
    for (int idx = tid; idx < 32 * 16; idx += 256) {
        const int i = idx >> 4;           // t row 0..31
        const int j = idx & 15;           // f pair 0..15
        const int t = t0 + i;
        const int f = f0 + 2 * j;
        const float v0 = tile[2 * j][i];
        const float v1 = tile[2 * j + 1][i];
        const __half h0a = __float2half_rn(v0);
        const __half h1a = __float2half_rn((v0 - __half2float(h0a)) * SPLIT_SCALE);
        const __half h0b = __float2half_rn(v1);
        const __half h1b = __float2half_rn((v1 - __half2float(h0b)) * SPLIT_SCALE);
        *(__half2*)&X0d[b][t][f] = __halves2half2(h0a, h0b);
        *(__half2*)&X1d[b][t][f] = __halves2half2(h1a, h1b);
    }
}
__global__ void split_w_kernel(const float* __restrict__ W) {
    __shared__ float tile[32][33];
    const int f0 = blockIdx.x * 32;
    const int u0 = blockIdx.y * 32;
    const int tx = threadIdx.x, ty = threadIdx.y;
    const int tid = ty * 32 + tx;
    for (int i = ty; i < 32; i += 8) {
        const int f = f0 + i;
        float v = 0.f;
        if (f < F_) v = W[(size_t)f * U_ + u0 + tx];
        tile[i][tx] = v;
    }
    __syncthreads();
    for (int idx = tid; idx < 32 * 16; idx += 256) {
        const int i = idx >> 4;           // u row
        const int j = idx & 15;           // f pair
        const int u = u0 + i;
        const int f = f0 + 2 * j;
        const float v0 = tile[2 * j][i];
        const float v1 = tile[2 * j + 1][i];
        const __half h0a = __float2half_rn(v0);
        const __half h1a = __float2half_rn((v0 - __half2float(h0a)) * SPLIT_SCALE);
        const __half h0b = __float2half_rn(v1);
        const __half h1b = __float2half_rn((v1 - __half2float(h0b)) * SPLIT_SCALE);
        *(__half2*)&W0d[u][f] = __halves2half2(h0a, h0b);
        *(__half2*)&W1d[u][f] = __halves2half2(h1a, h1b);
    }
}

// ---------------- chunk loader: 16 cp.async16 per thread ----------------
__device__ __forceinline__ void load_chunk(uint32_t sb, int stage, int p,
                                           int b, int u0, int tid) {
    const uint32_t st = sb + stage * STAGE_B;
    const int k0 = p * KC;
    const __half* src[4] = { &X0d[b][0][k0], &X1d[b][0][k0],
                             &W0d[u0][k0],  &W1d[u0][k0] };
#pragma unroll
    for (int arr = 0; arr < 4; ++arr) {
#pragma unroll
        for (int i = 0; i < 4; ++i) {
            const int u_  = tid + 256 * i;       // 0..1023
            const int row = u_ >> 3;             // 0..127
            const int c16 = u_ & 7;              // 16B unit within 128B row data
            cp_async16(st + arr * ARR_B + row * (ROWH * 2) + c16 * 16,
                       (const char*)src[arr] + (size_t)row * (KP * 2) + c16 * 16);
        }
    }
}

// ---------------- fused mma.sync GEMM + LIF scan ----------------
// Warp tile m32 x n64 (4 M-groups x 2 N-groups). Per-accumulator k16 order
// ascending and term order (a0b0; a0b1,a1b0,a1m*b1m) unchanged -> bit-identical
// to R11 (rel_err must be exactly 0.000991695).
__global__ __launch_bounds__(256, 1)
void snn_mma_kernel(float* __restrict__ out)
{
    extern __shared__ __align__(128) char smem[];
    const uint32_t sb = s2u(smem);
    const int tid = threadIdx.x;
    const int wid = tid >> 5;
    const int lid = tid & 31;
    const int u0  = blockIdx.x * NT;
    const int b   = blockIdx.y;
    const int m0  = (wid >> 1) * 32;          // warp M-base (4 groups)
    const int n0  = (wid & 1) * 64;           // warp N-base (2 groups)

    // accumulators: [mblk(2)][ntile(8)] x 4 regs, two sets
    float acc0[64], acc1[64];
#pragma unroll
    for (int i = 0; i < 64; ++i) { acc0[i] = 0.f; acc1[i] = 0.f; }

    // ldmatrix lane addressing
    const int ar = lid & 15;                  // A row within 16-block
    const int ac = (lid >> 4) & 1;            // k col-half
    const int brbase = (lid & 7) + ((lid & 16) ? 8 : 0);
    const int bc = (lid >> 3) & 1;

    load_chunk(sb, 0, 0, b, u0, tid);
    cp_commit();

    for (int p = 0; p < NCH; ++p) {
        const int s = p & 1;
        if (p + 1 < NCH) { load_chunk(sb, s ^ 1, p + 1, b, u0, tid); cp_commit(); }
        if (p + 1 < NCH) cp_wait1(); else cp_wait0();   // chunk p landed (mine)
        __syncthreads();                                 // everyone's landed

        const uint32_t st = sb + s * STAGE_B;
#pragma unroll
        for (int ks = 0; ks < 4; ++ks) {                 // four k16 steps
            uint32_t a0f[2][4], a1f[2][4], a1m[2][4];
#pragma unroll
            for (int blk = 0; blk < 2; ++blk) {
                const uint32_t aoff = st + (m0 + blk * 16 + ar) * (ROWH * 2)
                                    + ks * 32 + ac * 16;
                ldsm4(a0f[blk], aoff);                   // A0
                ldsm4(a1f[blk], aoff + ARR_B);           // A1 (residual*2048)
#pragma unroll
                for (int i = 0; i < 4; ++i) a1m[blk][i] = hmul2(a1f[blk][i], SCALE_A_2M5);
            }
#pragma unroll
            for (int j = 0; j < 4; ++j) {                // warp's 4 n-pairs
                uint32_t b0f[4], b1f[4], b1m[4];
                const uint32_t boff = st + 2 * ARR_B
                    + (n0 + j * 16 + brbase) * (ROWH * 2) + ks * 32 + bc * 16;
                ldsm4(b0f, boff);                        // W0
                ldsm4(b1f, boff + ARR_B);                // W1 (residual*2048)
#pragma unroll
                for (int i = 0; i < 4; ++i) b1m[i] = hmul2(b1f[i], SCALE_B_2M6);
#pragma unroll
                for (int blk = 0; blk < 2; ++blk) {
                    float* c0a = acc0 + (blk * 8 + 2 * j) * 4;
                    float* c1a = acc1 + (blk * 8 + 2 * j) * 4;
                    float* c0b = acc0 + (blk * 8 + 2 * j + 1) * 4;
                    float* c1b = acc1 + (blk * 8 + 2 * j + 1) * 4;
                    // n-tile 2j (frag regs [0],[1])
                    mma16816(c0a, a0f[blk], b0f);
                    mma16816(c1a, a0f[blk], b1f);
                    mma16816(c1a, a1f[blk], b0f);
                    mma16816(c1a, a1m[blk], b1m);
                    // n-tile 2j+1 (frag regs [2],[3])
                    mma16816(c0b, a0f[blk], b0f + 2);
                    mma16816(c1b, a0f[blk], b1f + 2);
                    mma16816(c1b, a1f[blk], b0f + 2);
                    mma16816(c1b, a1m[blk], b1m + 2);
                }
            }
        }
        if (p + 1 < NCH) __syncthreads();   // stage s reads done before iter p+1
    }

    // ---- epilogue: combine splits, park h in smem (aliases stages) ----
    __syncthreads();
    float* Cs = (float*)smem;               // [128][132]
    const int g  = lid >> 2;
    const int c2 = (lid & 3) * 2;
#pragma unroll
    for (int blk = 0; blk < 2; ++blk) {
#pragma unroll
        for (int nt = 0; nt < 8; ++nt) {
            const int col  = n0 + nt * 8 + c2;
            const int row0 = m0 + blk * 16 + g;
            const float* p0 = acc0 + (blk * 8 + nt) * 4;
            const float* p1 = acc1 + (blk * 8 + nt) * 4;
            float2 v0 = { p0[0] + p1[0] * INV_SCALE, p0[1] + p1[1] * INV_SCALE };
            float2 v1 = { p0[2] + p1[2] * INV_SCALE, p0[3] + p1[3] * INV_SCALE };
            *(float2*)&Cs[row0 * 132 + col]       = v0;
            *(float2*)&Cs[(row0 + 8) * 132 + col] = v1;
        }
    }
    __syncthreads();

    // ---- LIF scan over t; thread = u column (threads 0..127) ----
    if (tid < NT) {
        float* op = out + (size_t)b * T_ * U_ + u0 + tid;
        float syn = 0.f, mem = 0.f;
#pragma unroll 4
        for (int t = 0; t < T_; ++t) {
            const float h = Cs[t * 132 + tid];
            syn = ALPHA_ * syn + h;           // synaptic current decay
            mem = BETA_  * mem + syn;         // membrane decay
            const float spk = (mem - THRESH_ > 0.f) ? 1.f : 0.f;
            mem -= spk * THRESH_;             // soft reset
            op[(size_t)t * U_] = spk;
        }
    }
}

// ---------------- launch ----------------
extern "C" void kernel_launch(void* const* d_in, const int* in_sizes, int n_in,
                              void* d_out, int out_size) {
    (void)in_sizes; (void)n_in; (void)out_size;
    const float* x = (const float*)d_in[0];   // [B, F, T]
    const float* W = (const float*)d_in[1];   // [F, U]
    float* out = (float*)d_out;               // [B, T, U] float32

    cudaFuncSetAttribute(snn_mma_kernel,
                         cudaFuncAttributeMaxDynamicSharedMemorySize, SMEM_TOTAL);

    dim3 gx(KP / 32, T_ / 32, B_);            // 26 x 4 x 256
    split_x_kernel<<<gx, dim3(32, 8)>>>(x);
    dim3 gw(KP / 32, U_ / 32);                // 26 x 64
    split_w_kernel<<<gw, dim3(32, 8)>>>(W);

    dim3 grid(U_ / NT, B_);                   // 16 x 256 = 4096 CTAs
    snn_mma_kernel<<<grid, 256, SMEM_TOTAL>>>(out);
}